// round 1
// baseline (speedup 1.0000x reference)
#include <cuda_runtime.h>
#include <cuda_bf16.h>

#define T_STEPS 30
#define BATCH   16384
#define HID     100
#define NP      7
#define BB      64          // batch rows per block
#define NTHREADS 800        // 8 (batch groups) x 100 (hidden units)
#define NB      8           // batch rows per thread

// ---- scratch (device globals: allocation-free) ----
__device__ float g_v1[4 * HID];           // Wih1 @ W1
__device__ float g_u1[4 * HID];           // Wih1 @ b1 + bih1 + bhh1
__device__ float g_in2[BATCH * 4 * HID];  // last @ Wih2^T + bih2 + bhh2

__device__ __forceinline__ float sigf(float x) {
    float e = __expf(-x);
    return __fdividef(1.0f, 1.0f + e);
}
__device__ __forceinline__ float tanhf_(float x) {
    float e = __expf(-2.0f * x);
    return __fdividef(1.0f - e, 1.0f + e);
}

// ---- tiny precompute: v1/u1 (runs once per launch, trivial cost) ----
__global__ void precompute_kernel(const float* __restrict__ W1,
                                  const float* __restrict__ b1,
                                  const float* __restrict__ Wih1,
                                  const float* __restrict__ bih1,
                                  const float* __restrict__ bhh1) {
    int j = blockIdx.x * blockDim.x + threadIdx.x;
    if (j < 4 * HID) {
        float v = 0.f, u = 0.f;
        for (int k = 0; k < HID; k++) {
            float w = Wih1[j * HID + k];
            v += w * W1[k];
            u += w * b1[k];
        }
        g_v1[j] = v;
        g_u1[j] = u + bih1[j] + bhh1[j];
    }
}

// GEMM micro-tile: acc[g][i] += sum_k h[brow+i][k] * W[g*100+tk][k]
// W_sm rows padded to 101 floats -> lane bank stride 5 (conflict-free),
// h reads are warp-broadcast (lanes share tb).
__device__ __forceinline__ void gemm100(float acc[4][NB],
                                        const float* __restrict__ W_sm,
                                        const float* __restrict__ h_sm,
                                        int tk, int brow) {
    const float* w0 = W_sm + tk * 101;
    const float* w1 = w0 + 100 * 101;
    const float* w2 = w1 + 100 * 101;
    const float* w3 = w2 + 100 * 101;
    const float* hp = h_sm + brow * HID;
#pragma unroll 4
    for (int k = 0; k < HID; k++) {
        float wv0 = w0[k], wv1 = w1[k], wv2 = w2[k], wv3 = w3[k];
#pragma unroll
        for (int i = 0; i < NB; i++) {
            float hv = hp[i * HID + k];
            acc[0][i] += wv0 * hv;
            acc[1][i] += wv1 * hv;
            acc[2][i] += wv2 * hv;
            acc[3][i] += wv3 * hv;
        }
    }
}

// smem layout (floats):
//   W_sm  [0,       40400)   weights padded 400 x 101
//   h_sm  [40400,   46800)   64 x 100 hidden state
//   x_sm  [46800,   48720)   30 x 64 input scalars
//   W2_sm [48720,   53620)   7 x 700 FC2 weights
#define SMEM_FLOATS 53620

__global__ __launch_bounds__(NTHREADS, 1)
void lstm_main_kernel(const float* __restrict__ x,
                      const float* __restrict__ Whh1,
                      const float* __restrict__ Wih2,
                      const float* __restrict__ Whh2,
                      const float* __restrict__ bih2,
                      const float* __restrict__ bhh2,
                      const float* __restrict__ W2,
                      const float* __restrict__ b2,
                      float* __restrict__ out) {
    extern __shared__ float sm[];
    float* W_sm  = sm;
    float* h_sm  = sm + 40400;
    float* x_sm  = sm + 46800;
    float* W2_sm = sm + 48720;

    const int tid  = threadIdx.x;
    const int tk   = tid % HID;      // hidden unit owned by this thread
    const int tb   = tid / HID;      // batch group 0..7
    const int brow = tb * NB;
    const int b0   = blockIdx.x * BB;

    // ---- prologue: Whh1, x slice, zero h ----
    for (int idx = tid; idx < 4 * HID * HID; idx += NTHREADS) {
        int j = idx / HID, k = idx - j * HID;
        W_sm[j * 101 + k] = Whh1[idx];
    }
    for (int idx = tid; idx < T_STEPS * BB; idx += NTHREADS) {
        int t = idx >> 6, i = idx & 63;
        x_sm[idx] = x[t * BATCH + b0 + i];
    }
    for (int idx = tid; idx < BB * HID; idx += NTHREADS) h_sm[idx] = 0.f;

    float v1g[4], u1g[4];
#pragma unroll
    for (int g = 0; g < 4; g++) {
        v1g[g] = g_v1[g * HID + tk];
        u1g[g] = g_u1[g * HID + tk];
    }

    float c[NB];
#pragma unroll
    for (int i = 0; i < NB; i++) c[i] = 0.f;

    // FC2 accumulator: first 448 threads own one (batch,row=p) output cell
    float y_reg = 0.f;
    int yb = 0, yp = 0;
    if (tid < BB * NP) {
        yb = tid / NP;
        yp = tid - yb * NP;
        y_reg = b2[yp];
    }
    __syncthreads();

    // ================= layer 1: 30 recurrent steps =================
    for (int t = 0; t < T_STEPS; t++) {
        float acc[4][NB];
#pragma unroll
        for (int i = 0; i < NB; i++) {
            float xv = x_sm[t * BB + brow + i];
            acc[0][i] = u1g[0] + xv * v1g[0];
            acc[1][i] = u1g[1] + xv * v1g[1];
            acc[2][i] = u1g[2] + xv * v1g[2];
            acc[3][i] = u1g[3] + xv * v1g[3];
        }
        gemm100(acc, W_sm, h_sm, tk, brow);

        float hn[NB];
#pragma unroll
        for (int i = 0; i < NB; i++) {
            float ig = sigf(acc[0][i]);
            float fg = sigf(acc[1][i]);
            float gg = tanhf_(acc[2][i]);
            float og = sigf(acc[3][i]);
            c[i] = fg * c[i] + ig * gg;
            hn[i] = og * tanhf_(c[i]);
        }
        __syncthreads();   // all reads of h_sm done
#pragma unroll
        for (int i = 0; i < NB; i++) h_sm[(brow + i) * HID + tk] = hn[i];
        __syncthreads();   // new h visible
    }

    // ================= layer 2 input GEMM: in2 = last @ Wih2^T + u2 =================
    for (int idx = tid; idx < 4 * HID * HID; idx += NTHREADS) {
        int j = idx / HID, k = idx - j * HID;
        W_sm[j * 101 + k] = Wih2[idx];
    }
    for (int idx = tid; idx < NP * NP * HID; idx += NTHREADS) W2_sm[idx] = W2[idx];
    __syncthreads();
    {
        float acc[4][NB];
        float u2g[4];
#pragma unroll
        for (int g = 0; g < 4; g++)
            u2g[g] = bih2[g * HID + tk] + bhh2[g * HID + tk];
#pragma unroll
        for (int i = 0; i < NB; i++) {
            acc[0][i] = u2g[0]; acc[1][i] = u2g[1];
            acc[2][i] = u2g[2]; acc[3][i] = u2g[3];
        }
        gemm100(acc, W_sm, h_sm, tk, brow);   // h_sm == last
#pragma unroll
        for (int g = 0; g < 4; g++)
#pragma unroll
            for (int i = 0; i < NB; i++)
                g_in2[(b0 + brow + i) * (4 * HID) + g * HID + tk] = acc[g][i];
    }
    __syncthreads();
    for (int idx = tid; idx < 4 * HID * HID; idx += NTHREADS) {
        int j = idx / HID, k = idx - j * HID;
        W_sm[j * 101 + k] = Whh2[idx];
    }
    __syncthreads();

    // ================= layer 2: 7 recurrent steps + fused FC2 =================
    for (int p = 0; p < NP; p++) {
        float acc[4][NB];
#pragma unroll
        for (int g = 0; g < 4; g++)
#pragma unroll
            for (int i = 0; i < NB; i++)
                acc[g][i] = g_in2[(b0 + brow + i) * (4 * HID) + g * HID + tk];

        gemm100(acc, W_sm, h_sm, tk, brow);

        float hn[NB];
#pragma unroll
        for (int i = 0; i < NB; i++) {
            float ig = sigf(acc[0][i]);
            float fg = sigf(acc[1][i]);
            float gg = tanhf_(acc[2][i]);
            float og = sigf(acc[3][i]);
            c[i] = fg * c[i] + ig * gg;
            hn[i] = og * tanhf_(c[i]);
        }
        __syncthreads();
#pragma unroll
        for (int i = 0; i < NB; i++) h_sm[(brow + i) * HID + tk] = hn[i];
        __syncthreads();

        // FC2 partial: y[b][p_out] += sum_k h2[b][k] * W2[p_out][p*100+k]
        if (tid < BB * NP) {
            const float* w  = W2_sm + yp * (NP * HID) + p * HID;
            const float* hh = h_sm + yb * HID;
            float s = 0.f;
#pragma unroll 4
            for (int k = 0; k < HID; k++) s += hh[k] * w[k];
            y_reg += s;
        }
    }

    if (tid < BB * NP) out[(b0 + yb) * NP + yp] = sigf(y_reg);
}

extern "C" void kernel_launch(void* const* d_in, const int* in_sizes, int n_in,
                              void* d_out, int out_size) {
    const float* x    = (const float*)d_in[0];
    const float* W1   = (const float*)d_in[1];
    const float* b1   = (const float*)d_in[2];
    const float* Wih1 = (const float*)d_in[3];
    const float* Whh1 = (const float*)d_in[4];
    const float* bih1 = (const float*)d_in[5];
    const float* bhh1 = (const float*)d_in[6];
    const float* Wih2 = (const float*)d_in[7];
    const float* Whh2 = (const float*)d_in[8];
    const float* bih2 = (const float*)d_in[9];
    const float* bhh2 = (const float*)d_in[10];
    const float* W2   = (const float*)d_in[11];
    const float* b2   = (const float*)d_in[12];
    float* out = (float*)d_out;

    const size_t smem_bytes = SMEM_FLOATS * sizeof(float);   // 214,480 B
    cudaFuncSetAttribute(lstm_main_kernel,
                         cudaFuncAttributeMaxDynamicSharedMemorySize,
                         (int)smem_bytes);

    precompute_kernel<<<1, 512>>>(W1, b1, Wih1, bih1, bhh1);
    lstm_main_kernel<<<BATCH / BB, NTHREADS, smem_bytes>>>(
        x, Whh1, Wih2, Whh2, bih2, bhh2, W2, b2, out);
}